// round 1
// baseline (speedup 1.0000x reference)
#include <cuda_runtime.h>
#include <cstdint>

#define BT_TOTAL 4096
#define T_SEQ    2048
#define EMB      2048
#define FD       3072
#define NH       32
#define NG       8
#define HD       64

// ---------------- device scratch (no allocations allowed) ----------------
__device__ float g_qkv[(size_t)BT_TOTAL * FD];             // 50.3 MB
__device__ float g_q[(size_t)2 * NH * T_SEQ * HD];         // 33.5 MB
__device__ float g_k[(size_t)2 * NG * T_SEQ * HD];         // 8.4 MB
__device__ float g_v[(size_t)2 * NG * T_SEQ * HD];         // 8.4 MB
__device__ float g_att[(size_t)BT_TOTAL * EMB];            // 33.5 MB

// ---------------- SGEMM: C[M,N] = A[M,K] @ B[N,K]^T ----------------
// 128x128 block tile, BK=8, 256 threads, 8x8 micro-tile, float4 loads.
__global__ __launch_bounds__(256, 2) void sgemm_nt(const float* __restrict__ A,
                                                   const float* __restrict__ B,
                                                   float* __restrict__ C,
                                                   int M, int N, int K) {
    __shared__ float As[8][128];
    __shared__ float Bs[8][128];
    const int tid  = threadIdx.x;
    const int bm   = blockIdx.y * 128;
    const int bn   = blockIdx.x * 128;
    const int tRow = tid >> 4;       // 0..15
    const int tCol = tid & 15;       // 0..15
    const int lRow = tid >> 1;       // 0..127
    const int lCol = (tid & 1) << 2; // 0 or 4

    const float* Ap = A + (size_t)(bm + lRow) * K + lCol;
    const float* Bp = B + (size_t)(bn + lRow) * K + lCol;

    float acc[8][8];
#pragma unroll
    for (int i = 0; i < 8; i++)
#pragma unroll
        for (int j = 0; j < 8; j++) acc[i][j] = 0.f;

    for (int k0 = 0; k0 < K; k0 += 8) {
        float4 av = *(const float4*)(Ap + k0);
        float4 bv = *(const float4*)(Bp + k0);
        As[lCol + 0][lRow] = av.x; As[lCol + 1][lRow] = av.y;
        As[lCol + 2][lRow] = av.z; As[lCol + 3][lRow] = av.w;
        Bs[lCol + 0][lRow] = bv.x; Bs[lCol + 1][lRow] = bv.y;
        Bs[lCol + 2][lRow] = bv.z; Bs[lCol + 3][lRow] = bv.w;
        __syncthreads();
#pragma unroll
        for (int k = 0; k < 8; k++) {
            float ra[8], rb[8];
            *(float4*)&ra[0] = *(const float4*)&As[k][tRow * 8];
            *(float4*)&ra[4] = *(const float4*)&As[k][tRow * 8 + 4];
            *(float4*)&rb[0] = *(const float4*)&Bs[k][tCol * 8];
            *(float4*)&rb[4] = *(const float4*)&Bs[k][tCol * 8 + 4];
#pragma unroll
            for (int i = 0; i < 8; i++)
#pragma unroll
                for (int j = 0; j < 8; j++)
                    acc[i][j] += ra[i] * rb[j];
        }
        __syncthreads();
    }
#pragma unroll
    for (int i = 0; i < 8; i++) {
        float* Cp = C + (size_t)(bm + tRow * 8 + i) * N + bn + tCol * 8;
        *(float4*)(Cp)     = make_float4(acc[i][0], acc[i][1], acc[i][2], acc[i][3]);
        *(float4*)(Cp + 4) = make_float4(acc[i][4], acc[i][5], acc[i][6], acc[i][7]);
    }
}

// ---------------- RoPE + scatter qkv -> q/k/v ----------------
// qkv[bt][f], f = (g*6 + slot)*64 + d. slots 0..3 -> q heads, 4 -> k, 5 -> v.
// Half-split rope: y1 = x1*c - x2*s ; y2 = x2*c + x1*s  (pairs d, d+32).
__global__ void rope_scatter(const float* __restrict__ qkv,
                             const float* __restrict__ cosb,
                             const float* __restrict__ sinb) {
    int idx = blockIdx.x * blockDim.x + threadIdx.x;
    const int total = BT_TOTAL * NG * 6 * 32;
    if (idx >= total) return;
    int dh = idx & 31;
    int r = idx >> 5;
    int slot = r % 6; r /= 6;
    int g = r % NG;   r /= NG;
    int bt = r;
    int t = bt & (T_SEQ - 1);
    int b = bt >> 11;

    const float* src = qkv + (size_t)bt * FD + (g * 6 + slot) * HD;
    float x1 = src[dh], x2 = src[dh + 32];
    if (slot == 5) {
        float* dst = g_v + ((size_t)(b * NG + g) * T_SEQ + t) * HD;
        dst[dh] = x1; dst[dh + 32] = x2;
    } else {
        float c = cosb[t * 32 + dh], s = sinb[t * 32 + dh];
        float y1 = x1 * c - x2 * s;
        float y2 = x2 * c + x1 * s;
        float* dst;
        if (slot == 4) dst = g_k + ((size_t)(b * NG + g) * T_SEQ + t) * HD;
        else           dst = g_q + ((size_t)(b * NH + g * 4 + slot) * T_SEQ + t) * HD;
        dst[dh] = y1; dst[dh + 32] = y2;
    }
}

// ---------------- Flash attention (fp32, non-causal) ----------------
// Block: 128 threads. Br=Bc=64. One (b,h) x query-tile per block.
// Q/K tiles stored d-major with XOR swizzle (phys row = r ^ (d & 60)) to keep
// both the transpose stores (2-way max) and compute float4 loads conflict-light.
__global__ __launch_bounds__(128) void attn_kernel(float* __restrict__ Oout) {
    extern __shared__ float sm[];
    float* Qs   = sm;              // [d][r] swizzled, 4096
    float* Ks   = Qs + 4096;       // [d][c] swizzled, 4096
    float* Vs   = Ks + 4096;       // [key][d], 4096
    float* Ps   = Vs + 4096;       // [64][65]
    float* m_s  = Ps + 64 * 65;    // [64]
    float* l_s  = m_s + 64;        // [64]
    float* al_s = l_s + 64;        // [64]

    const int tid = threadIdx.x;
    const int qt  = blockIdx.x;
    const int bh  = blockIdx.y;
    const int b   = bh >> 5;
    const int h   = bh & 31;
    const int g   = h >> 2;
    const int q0  = qt * 64;

    const float* qbase = g_q + ((size_t)(b * NH + h) * T_SEQ + q0) * HD;
    const float* kbase = g_k + (size_t)(b * NG + g) * T_SEQ * HD;
    const float* vbase = g_v + (size_t)(b * NG + g) * T_SEQ * HD;

    // load Q tile, transposed + swizzled
#pragma unroll
    for (int it = 0; it < 8; it++) {
        int idx = it * 128 + tid;
        int r   = idx >> 4;
        int d4  = (idx & 15) << 2;     // swizzle key = d4 (== d & 60 for this group)
        float4 v = *(const float4*)(qbase + r * 64 + d4);
        int pr = r ^ d4;
        Qs[(d4 + 0) * 64 + pr] = v.x;
        Qs[(d4 + 1) * 64 + pr] = v.y;
        Qs[(d4 + 2) * 64 + pr] = v.z;
        Qs[(d4 + 3) * 64 + pr] = v.w;
    }
    if (tid < 64) { m_s[tid] = -1e30f; l_s[tid] = 0.f; }

    const int tr = tid >> 4;  // 0..7  -> rows tr*8 .. tr*8+7
    const int tc = tid & 15;  // 0..15 -> cols tc*4 .. tc*4+3
    float Oacc[8][4];
#pragma unroll
    for (int i = 0; i < 8; i++)
#pragma unroll
        for (int j = 0; j < 4; j++) Oacc[i][j] = 0.f;

    const float scale = 0.125f; // 1/sqrt(64)

    for (int kt = 0; kt < T_SEQ / 64; kt++) {
        const float* kb = kbase + (size_t)kt * 64 * 64;
        const float* vb = vbase + (size_t)kt * 64 * 64;
        __syncthreads();  // previous PV done before K/V/Ps overwritten
#pragma unroll
        for (int it = 0; it < 8; it++) {
            int idx = it * 128 + tid;
            int c   = idx >> 4;
            int d4  = (idx & 15) << 2;
            float4 kv = *(const float4*)(kb + c * 64 + d4);
            int pc = c ^ d4;
            Ks[(d4 + 0) * 64 + pc] = kv.x;
            Ks[(d4 + 1) * 64 + pc] = kv.y;
            Ks[(d4 + 2) * 64 + pc] = kv.z;
            Ks[(d4 + 3) * 64 + pc] = kv.w;
            float4 vv = *(const float4*)(vb + c * 64 + d4);
            *(float4*)&Vs[c * 64 + d4] = vv;
        }
        __syncthreads();

        // S = Q K^T (register tile 8x4 per thread)
        float sacc[8][4];
#pragma unroll
        for (int i = 0; i < 8; i++)
#pragma unroll
            for (int j = 0; j < 4; j++) sacc[i][j] = 0.f;

#pragma unroll 16
        for (int d = 0; d < 64; d++) {
            int sw = d & 60;
            float ra[8], rb[4];
            int p1 = (tr * 8) ^ sw;
            *(float4*)&ra[0] = *(const float4*)&Qs[d * 64 + p1];
            *(float4*)&ra[4] = *(const float4*)&Qs[d * 64 + (p1 ^ 4)];
            *(float4*)&rb[0] = *(const float4*)&Ks[d * 64 + ((tc * 4) ^ sw)];
#pragma unroll
            for (int i = 0; i < 8; i++)
#pragma unroll
                for (int j = 0; j < 4; j++)
                    sacc[i][j] += ra[i] * rb[j];
        }
#pragma unroll
        for (int i = 0; i < 8; i++)
#pragma unroll
            for (int j = 0; j < 4; j++)
                Ps[(tr * 8 + i) * 65 + tc * 4 + j] = sacc[i][j] * scale;
        __syncthreads();

        // online softmax: one thread per row
        if (tid < 64) {
            float mo = m_s[tid];
            float mn = mo;
            float* pr = Ps + tid * 65;
#pragma unroll 8
            for (int c2 = 0; c2 < 64; c2++) mn = fmaxf(mn, pr[c2]);
            float sum = 0.f;
#pragma unroll 8
            for (int c2 = 0; c2 < 64; c2++) {
                float p = __expf(pr[c2] - mn);
                pr[c2] = p;
                sum += p;
            }
            float al = __expf(mo - mn);
            l_s[tid]  = l_s[tid] * al + sum;
            m_s[tid]  = mn;
            al_s[tid] = al;
        }
        __syncthreads();

        // rescale O, then O += P @ V
#pragma unroll
        for (int i = 0; i < 8; i++) {
            float al = al_s[tr * 8 + i];
#pragma unroll
            for (int j = 0; j < 4; j++) Oacc[i][j] *= al;
        }
#pragma unroll 16
        for (int k = 0; k < 64; k++) {
            float rp[8], rv[4];
#pragma unroll
            for (int i = 0; i < 8; i++) rp[i] = Ps[(tr * 8 + i) * 65 + k];
            *(float4*)&rv[0] = *(const float4*)&Vs[k * 64 + tc * 4];
#pragma unroll
            for (int i = 0; i < 8; i++)
#pragma unroll
                for (int j = 0; j < 4; j++)
                    Oacc[i][j] += rp[i] * rv[j];
        }
    }

    // epilogue: divide by l, write [B][T][H*D]
#pragma unroll
    for (int i = 0; i < 8; i++) {
        float inv = 1.f / l_s[tr * 8 + i];
        float4 o = make_float4(Oacc[i][0] * inv, Oacc[i][1] * inv,
                               Oacc[i][2] * inv, Oacc[i][3] * inv);
        float* dst = g_att + ((size_t)b * T_SEQ + q0 + tr * 8 + i) * EMB + h * 64 + tc * 4;
        *(float4*)dst = o;
    }
}

// ---------------- launch ----------------
extern "C" void kernel_launch(void* const* d_in, const int* in_sizes, int n_in,
                              void* d_out, int out_size) {
    const float* x      = (const float*)d_in[0];
    const float* cosb   = (const float*)d_in[1];
    const float* sinb   = (const float*)d_in[2];
    const float* attn_w = (const float*)d_in[3];
    const float* proj_w = (const float*)d_in[4];
    float* out = (float*)d_out;

    float *qkv, *att;
    cudaGetSymbolAddress((void**)&qkv, g_qkv);
    cudaGetSymbolAddress((void**)&att, g_att);

    // 1) qkv = x @ attn_w^T   [4096,3072]
    sgemm_nt<<<dim3(FD / 128, BT_TOTAL / 128), 256>>>(x, attn_w, qkv, BT_TOTAL, FD, EMB);

    // 2) rope + scatter to q/k/v
    {
        int total = BT_TOTAL * NG * 6 * 32;
        rope_scatter<<<(total + 255) / 256, 256>>>(qkv, cosb, sinb);
    }

    // 3) flash attention -> g_att [B,T,H*D]
    {
        const int smem_bytes = (3 * 4096 + 64 * 65 + 3 * 64) * 4; // 66560
        cudaFuncSetAttribute(attn_kernel, cudaFuncAttributeMaxDynamicSharedMemorySize, smem_bytes);
        attn_kernel<<<dim3(T_SEQ / 64, 2 * NH), 128, smem_bytes>>>(att);
    }

    // 4) out = att @ proj_w^T  [4096,2048]
    sgemm_nt<<<dim3(EMB / 128, BT_TOTAL / 128), 256>>>(att, proj_w, out, BT_TOTAL, EMB, EMB);
}

// round 7
// speedup vs baseline: 1.5503x; 1.5503x over previous
#include <cuda_runtime.h>
#include <cuda_bf16.h>
#include <cstdint>

#define BT_TOTAL 4096
#define T_SEQ    2048
#define EMB      2048
#define FD       3072
#define NH       32
#define NG       8
#define HD       64
#define KEXT     6144           // 3 * EMB (hi | lo | hi) extended K
#define GBK      64
#define NCH      (KEXT / GBK)   // 96

// ---------------- device scratch (no allocations allowed) ----------------
__device__ float g_qkv[(size_t)BT_TOTAL * FD];
__device__ float g_q[(size_t)2 * NH * T_SEQ * HD];
__device__ float g_k[(size_t)2 * NG * T_SEQ * HD];
__device__ float g_v[(size_t)2 * NG * T_SEQ * HD];
__device__ float g_att[(size_t)BT_TOTAL * EMB];

__device__ __nv_bfloat16 g_xe[(size_t)BT_TOTAL * KEXT];   // x extended
__device__ __nv_bfloat16 g_w1e[(size_t)FD * KEXT];        // attn_w extended
__device__ __nv_bfloat16 g_w2e[(size_t)EMB * KEXT];       // proj_w extended
__device__ __nv_bfloat16 g_ae[(size_t)BT_TOTAL * KEXT];   // att extended

// ---------------- helpers ----------------
__device__ __forceinline__ uint32_t smem_u32(const void* p) {
    uint32_t a;
    asm("{ .reg .u64 t; cvta.to.shared.u64 t, %1; cvt.u32.u64 %0, t; }" : "=r"(a) : "l"(p));
    return a;
}
__device__ __forceinline__ void cp16(uint32_t dst, const void* src) {
    asm volatile("cp.async.cg.shared.global [%0], [%1], 16;" :: "r"(dst), "l"(src));
}
__device__ __forceinline__ void ldsm_x4(uint32_t addr, uint32_t* r) {
    asm volatile("ldmatrix.sync.aligned.m8n8.x4.shared.b16 {%0,%1,%2,%3}, [%4];"
        : "=r"(r[0]), "=r"(r[1]), "=r"(r[2]), "=r"(r[3]) : "r"(addr));
}
__device__ __forceinline__ void ldsm_x2(uint32_t addr, uint32_t* r) {
    asm volatile("ldmatrix.sync.aligned.m8n8.x2.shared.b16 {%0,%1}, [%2];"
        : "=r"(r[0]), "=r"(r[1]) : "r"(addr));
}
__device__ __forceinline__ void mma_bf16(float* c, const uint32_t* a, const uint32_t* b) {
    asm volatile("mma.sync.aligned.m16n8k16.row.col.f32.bf16.bf16.f32 "
        "{%0,%1,%2,%3}, {%4,%5,%6,%7}, {%8,%9}, {%0,%1,%2,%3};"
        : "+f"(c[0]), "+f"(c[1]), "+f"(c[2]), "+f"(c[3])
        : "r"(a[0]), "r"(a[1]), "r"(a[2]), "r"(a[3]), "r"(b[0]), "r"(b[1]));
}

// ---------------- split fp32 [R][2048] -> extended bf16 [R][6144] ----------------
// hi written at col k and col hi2_off+k ; lo written at col lo_off+k.
__global__ void split_ext(const float* __restrict__ src, __nv_bfloat16* __restrict__ dst,
                          int n4, int hi2_off, int lo_off) {
    int i = blockIdx.x * blockDim.x + threadIdx.x;
    if (i >= n4) return;
    int c4 = (i & 511) << 2;        // 0..2044 step 4
    int r  = i >> 9;
    float4 v = *(const float4*)(src + (size_t)r * EMB + c4);
    __nv_bfloat16 h0 = __float2bfloat16(v.x), h1 = __float2bfloat16(v.y);
    __nv_bfloat16 h2 = __float2bfloat16(v.z), h3 = __float2bfloat16(v.w);
    __nv_bfloat16 l0 = __float2bfloat16(v.x - __bfloat162float(h0));
    __nv_bfloat16 l1 = __float2bfloat16(v.y - __bfloat162float(h1));
    __nv_bfloat16 l2 = __float2bfloat16(v.z - __bfloat162float(h2));
    __nv_bfloat16 l3 = __float2bfloat16(v.w - __bfloat162float(h3));
    __nv_bfloat162 H01(h0, h1), H23(h2, h3), L01(l0, l1), L23(l2, l3);
    size_t rowb = (size_t)r * KEXT;
    __nv_bfloat162* p0 = (__nv_bfloat162*)(dst + rowb + c4);
    __nv_bfloat162* p1 = (__nv_bfloat162*)(dst + rowb + hi2_off + c4);
    __nv_bfloat162* p2 = (__nv_bfloat162*)(dst + rowb + lo_off + c4);
    p0[0] = H01; p0[1] = H23;
    p1[0] = H01; p1[1] = H23;
    p2[0] = L01; p2[1] = L23;
}

// ---------------- HMMA GEMM: C[M,N] = A[M,KEXT] @ B[N,KEXT]^T ----------------
// 256 threads, 128x128 tile, BK=64, 3-stage cp.async, warp tile 32x64.
#define GEMM_SMEM (3 * 32768)
__global__ __launch_bounds__(256, 1) void gemm_hmma(
    const __nv_bfloat16* __restrict__ A, const __nv_bfloat16* __restrict__ B,
    float* __restrict__ C, int N) {
    extern __shared__ __align__(1024) char smem[];
    const uint32_t sbase = smem_u32(smem);
    const int tid = threadIdx.x;
    const int wid = tid >> 5, lane = tid & 31;
    const int bm = blockIdx.y * 128, bn = blockIdx.x * 128;
    const int warp_m = wid & 3, warp_n = wid >> 2;

    auto load_chunk = [&](int chunk, int stage) {
        const uint32_t sA = sbase + stage * 32768;
        const uint32_t sB = sA + 16384;
#pragma unroll
        for (int i = 0; i < 4; i++) {
            int id = i * 256 + tid;
            int row = id >> 3, c16 = id & 7;
            uint32_t off = (uint32_t)(row * 128 + ((c16 ^ (row & 7)) << 4));
            cp16(sA + off, A + (size_t)(bm + row) * KEXT + chunk * GBK + c16 * 8);
        }
#pragma unroll
        for (int i = 0; i < 4; i++) {
            int id = i * 256 + tid;
            int row = id >> 3, c16 = id & 7;
            uint32_t off = (uint32_t)(row * 128 + ((c16 ^ (row & 7)) << 4));
            cp16(sB + off, B + (size_t)(bn + row) * KEXT + chunk * GBK + c16 * 8);
        }
        asm volatile("cp.async.commit_group;" ::: "memory");
    };

    float acc[2][8][4];
#pragma unroll
    for (int mf = 0; mf < 2; mf++)
#pragma unroll
        for (int nf = 0; nf < 8; nf++)
#pragma unroll
            for (int q = 0; q < 4; q++) acc[mf][nf][q] = 0.f;

    load_chunk(0, 0);
    load_chunk(1, 1);

    for (int c = 0; c < NCH; c++) {
        __syncthreads();
        if (c + 2 < NCH) load_chunk(c + 2, (c + 2) % 3);
        else asm volatile("cp.async.commit_group;" ::: "memory");
        asm volatile("cp.async.wait_group 2;" ::: "memory");
        __syncthreads();

        const uint32_t sA = sbase + (c % 3) * 32768;
        const uint32_t sB = sA + 16384;
#pragma unroll
        for (int kf = 0; kf < 4; kf++) {
            uint32_t afr[2][4];
#pragma unroll
            for (int mf = 0; mf < 2; mf++) {
                int row = warp_m * 32 + mf * 16 + (lane & 15);
                int c16 = kf * 2 + (lane >> 4);
                ldsm_x4(sA + row * 128 + ((c16 ^ (row & 7)) << 4), afr[mf]);
            }
#pragma unroll
            for (int nf = 0; nf < 8; nf++) {
                uint32_t bfr[2];
                int nrow = warp_n * 64 + nf * 8 + (lane & 7);
                int c16 = kf * 2 + ((lane >> 3) & 1);
                ldsm_x2(sB + nrow * 128 + ((c16 ^ (nrow & 7)) << 4), bfr);
                mma_bf16(acc[0][nf], afr[0], bfr);
                mma_bf16(acc[1][nf], afr[1], bfr);
            }
        }
    }

    // epilogue
#pragma unroll
    for (int mf = 0; mf < 2; mf++) {
        int row = bm + warp_m * 32 + mf * 16 + (lane >> 2);
#pragma unroll
        for (int nf = 0; nf < 8; nf++) {
            int col = bn + warp_n * 64 + nf * 8 + (lane & 3) * 2;
            *(float2*)(C + (size_t)row * N + col)       = make_float2(acc[mf][nf][0], acc[mf][nf][1]);
            *(float2*)(C + (size_t)(row + 8) * N + col) = make_float2(acc[mf][nf][2], acc[mf][nf][3]);
        }
    }
}

// ---------------- RoPE + scatter qkv -> q/k/v ----------------
__global__ void rope_scatter(const float* __restrict__ qkv,
                             const float* __restrict__ cosb,
                             const float* __restrict__ sinb) {
    int idx = blockIdx.x * blockDim.x + threadIdx.x;
    const int total = BT_TOTAL * NG * 6 * 32;
    if (idx >= total) return;
    int dh = idx & 31;
    int r = idx >> 5;
    int slot = r % 6; r /= 6;
    int g = r % NG;   r /= NG;
    int bt = r;
    int t = bt & (T_SEQ - 1);
    int b = bt >> 11;

    const float* src = qkv + (size_t)bt * FD + (g * 6 + slot) * HD;
    float x1 = src[dh], x2 = src[dh + 32];
    if (slot == 5) {
        float* dst = g_v + ((size_t)(b * NG + g) * T_SEQ + t) * HD;
        dst[dh] = x1; dst[dh + 32] = x2;
    } else {
        float c = cosb[t * 32 + dh], s = sinb[t * 32 + dh];
        float y1 = x1 * c - x2 * s;
        float y2 = x2 * c + x1 * s;
        float* dst;
        if (slot == 4) dst = g_k + ((size_t)(b * NG + g) * T_SEQ + t) * HD;
        else           dst = g_q + ((size_t)(b * NH + g * 4 + slot) * T_SEQ + t) * HD;
        dst[dh] = y1; dst[dh + 32] = y2;
    }
}

// ---------------- Flash attention (fp32, non-causal) ----------------
__global__ __launch_bounds__(128) void attn_kernel(float* __restrict__ Oout) {
    extern __shared__ float sm[];
    float* Qs   = sm;
    float* Ks   = Qs + 4096;
    float* Vs   = Ks + 4096;
    float* Ps   = Vs + 4096;
    float* m_s  = Ps + 64 * 65;
    float* l_s  = m_s + 64;
    float* al_s = l_s + 64;

    const int tid = threadIdx.x;
    const int qt  = blockIdx.x;
    const int bh  = blockIdx.y;
    const int b   = bh >> 5;
    const int h   = bh & 31;
    const int g   = h >> 2;
    const int q0  = qt * 64;

    const float* qbase = g_q + ((size_t)(b * NH + h) * T_SEQ + q0) * HD;
    const float* kbase = g_k + (size_t)(b * NG + g) * T_SEQ * HD;
    const float* vbase = g_v + (size_t)(b * NG + g) * T_SEQ * HD;

#pragma unroll
    for (int it = 0; it < 8; it++) {
        int idx = it * 128 + tid;
        int r   = idx >> 4;
        int d4  = (idx & 15) << 2;
        float4 v = *(const float4*)(qbase + r * 64 + d4);
        int pr = r ^ d4;
        Qs[(d4 + 0) * 64 + pr] = v.x;
        Qs[(d4 + 1) * 64 + pr] = v.y;
        Qs[(d4 + 2) * 64 + pr] = v.z;
        Qs[(d4 + 3) * 64 + pr] = v.w;
    }
    if (tid < 64) { m_s[tid] = -1e30f; l_s[tid] = 0.f; }

    const int tr = tid >> 4;
    const int tc = tid & 15;
    float Oacc[8][4];
#pragma unroll
    for (int i = 0; i < 8; i++)
#pragma unroll
        for (int j = 0; j < 4; j++) Oacc[i][j] = 0.f;

    const float scale = 0.125f;

    for (int kt = 0; kt < T_SEQ / 64; kt++) {
        const float* kb = kbase + (size_t)kt * 64 * 64;
        const float* vb = vbase + (size_t)kt * 64 * 64;
        __syncthreads();
#pragma unroll
        for (int it = 0; it < 8; it++) {
            int idx = it * 128 + tid;
            int c   = idx >> 4;
            int d4  = (idx & 15) << 2;
            float4 kv = *(const float4*)(kb + c * 64 + d4);
            int pc = c ^ d4;
            Ks[(d4 + 0) * 64 + pc] = kv.x;
            Ks[(d4 + 1) * 64 + pc] = kv.y;
            Ks[(d4 + 2) * 64 + pc] = kv.z;
            Ks[(d4 + 3) * 64 + pc] = kv.w;
            float4 vv = *(const float4*)(vb + c * 64 + d4);
            *(float4*)&Vs[c * 64 + d4] = vv;
        }
        __syncthreads();

        float sacc[8][4];
#pragma unroll
        for (int i = 0; i < 8; i++)
#pragma unroll
            for (int j = 0; j < 4; j++) sacc[i][j] = 0.f;

#pragma unroll 16
        for (int d = 0; d < 64; d++) {
            int sw = d & 60;
            float ra[8], rb[4];
            int p1 = (tr * 8) ^ sw;
            *(float4*)&ra[0] = *(const float4*)&Qs[d * 64 + p1];
            *(float4*)&ra[4] = *(const float4*)&Qs[d * 64 + (p1 ^ 4)];
            *(float4*)&rb[0] = *(const float4*)&Ks[d * 64 + ((tc * 4) ^ sw)];
#pragma unroll
            for (int i = 0; i < 8; i++)
#pragma unroll
                for (int j = 0; j < 4; j++)
                    sacc[i][j] += ra[i] * rb[j];
        }
#pragma unroll
        for (int i = 0; i < 8; i++)
#pragma unroll
            for (int j = 0; j < 4; j++)
                Ps[(tr * 8 + i) * 65 + tc * 4 + j] = sacc[i][j] * scale;
        __syncthreads();

        if (tid < 64) {
            float mo = m_s[tid];
            float mn = mo;
            float* pr = Ps + tid * 65;
#pragma unroll 8
            for (int c2 = 0; c2 < 64; c2++) mn = fmaxf(mn, pr[c2]);
            float sum = 0.f;
#pragma unroll 8
            for (int c2 = 0; c2 < 64; c2++) {
                float p = __expf(pr[c2] - mn);
                pr[c2] = p;
                sum += p;
            }
            float al = __expf(mo - mn);
            l_s[tid]  = l_s[tid] * al + sum;
            m_s[tid]  = mn;
            al_s[tid] = al;
        }
        __syncthreads();

#pragma unroll
        for (int i = 0; i < 8; i++) {
            float al = al_s[tr * 8 + i];
#pragma unroll
            for (int j = 0; j < 4; j++) Oacc[i][j] *= al;
        }
#pragma unroll 16
        for (int k = 0; k < 64; k++) {
            float rp[8], rv[4];
#pragma unroll
            for (int i = 0; i < 8; i++) rp[i] = Ps[(tr * 8 + i) * 65 + k];
            *(float4*)&rv[0] = *(const float4*)&Vs[k * 64 + tc * 4];
#pragma unroll
            for (int i = 0; i < 8; i++)
#pragma unroll
                for (int j = 0; j < 4; j++)
                    Oacc[i][j] += rp[i] * rv[j];
        }
    }

#pragma unroll
    for (int i = 0; i < 8; i++) {
        float inv = 1.f / l_s[tr * 8 + i];
        float4 o = make_float4(Oacc[i][0] * inv, Oacc[i][1] * inv,
                               Oacc[i][2] * inv, Oacc[i][3] * inv);
        float* dst = g_att + ((size_t)b * T_SEQ + q0 + tr * 8 + i) * EMB + h * 64 + tc * 4;
        *(float4*)dst = o;
    }
}

// ---------------- launch ----------------
extern "C" void kernel_launch(void* const* d_in, const int* in_sizes, int n_in,
                              void* d_out, int out_size) {
    const float* x      = (const float*)d_in[0];
    const float* cosb   = (const float*)d_in[1];
    const float* sinb   = (const float*)d_in[2];
    const float* attn_w = (const float*)d_in[3];
    const float* proj_w = (const float*)d_in[4];
    float* out = (float*)d_out;

    float *qkv, *att;
    __nv_bfloat16 *xe, *w1e, *w2e, *ae;
    cudaGetSymbolAddress((void**)&qkv, g_qkv);
    cudaGetSymbolAddress((void**)&att, g_att);
    cudaGetSymbolAddress((void**)&xe, g_xe);
    cudaGetSymbolAddress((void**)&w1e, g_w1e);
    cudaGetSymbolAddress((void**)&w2e, g_w2e);
    cudaGetSymbolAddress((void**)&ae, g_ae);

    cudaFuncSetAttribute(gemm_hmma, cudaFuncAttributeMaxDynamicSharedMemorySize, GEMM_SMEM);

    // split inputs into extended bf16 operands
    // A-type (activations): [hi | lo | hi]  -> hi2_off = 2*EMB, lo_off = EMB
    // B-type (weights):     [hi | hi | lo]  -> hi2_off = EMB,   lo_off = 2*EMB
    {
        int n4 = BT_TOTAL * 512;
        split_ext<<<(n4 + 255) / 256, 256>>>(x, xe, n4, 2 * EMB, EMB);
        n4 = FD * 512;
        split_ext<<<(n4 + 255) / 256, 256>>>(attn_w, w1e, n4, EMB, 2 * EMB);
        n4 = EMB * 512;
        split_ext<<<(n4 + 255) / 256, 256>>>(proj_w, w2e, n4, EMB, 2 * EMB);
    }

    // 1) qkv = x @ attn_w^T   [4096,3072]
    gemm_hmma<<<dim3(FD / 128, BT_TOTAL / 128), 256, GEMM_SMEM>>>(xe, w1e, qkv, FD);

    // 2) rope + scatter
    {
        int total = BT_TOTAL * NG * 6 * 32;
        rope_scatter<<<(total + 255) / 256, 256>>>(qkv, cosb, sinb);
    }

    // 3) flash attention -> g_att
    {
        const int smem_bytes = (3 * 4096 + 64 * 65 + 3 * 64) * 4;
        cudaFuncSetAttribute(attn_kernel, cudaFuncAttributeMaxDynamicSharedMemorySize, smem_bytes);
        attn_kernel<<<dim3(T_SEQ / 64, 2 * NH), 128, smem_bytes>>>(att);
    }

    // 4) split attention output, then out = att @ proj_w^T  [4096,2048]
    {
        int n4 = BT_TOTAL * 512;
        split_ext<<<(n4 + 255) / 256, 256>>>(att, ae, n4, 2 * EMB, EMB);
    }
    gemm_hmma<<<dim3(EMB / 128, BT_TOTAL / 128), 256, GEMM_SMEM>>>(ae, w2e, out, EMB);
}

// round 8
// speedup vs baseline: 3.3261x; 2.1455x over previous
#include <cuda_runtime.h>
#include <cuda_bf16.h>
#include <cuda_fp16.h>
#include <cstdint>

#define BT_TOTAL 4096
#define T_SEQ    2048
#define EMB      2048
#define FD       3072
#define NH       32
#define NG       8
#define HD       64
#define KEXT     6144           // 3 * EMB (hi | lo | hi) extended K
#define GBK      64
#define NCH      (KEXT / GBK)   // 96

// ---------------- device scratch (no allocations allowed) ----------------
__device__ float g_qkv[(size_t)BT_TOTAL * FD];

__device__ __half g_qh[(size_t)2 * NH * T_SEQ * HD];
__device__ __half g_ql[(size_t)2 * NH * T_SEQ * HD];
__device__ __half g_kh[(size_t)2 * NG * T_SEQ * HD];
__device__ __half g_vh[(size_t)2 * NG * T_SEQ * HD];

__device__ __nv_bfloat16 g_xe[(size_t)BT_TOTAL * KEXT];   // x extended
__device__ __nv_bfloat16 g_w1e[(size_t)FD * KEXT];        // attn_w extended
__device__ __nv_bfloat16 g_w2e[(size_t)EMB * KEXT];       // proj_w extended
__device__ __nv_bfloat16 g_ae[(size_t)BT_TOTAL * KEXT];   // att extended

// ---------------- helpers ----------------
__device__ __forceinline__ uint32_t smem_u32(const void* p) {
    uint32_t a;
    asm("{ .reg .u64 t; cvta.to.shared.u64 t, %1; cvt.u32.u64 %0, t; }" : "=r"(a) : "l"(p));
    return a;
}
__device__ __forceinline__ void cp16(uint32_t dst, const void* src) {
    asm volatile("cp.async.cg.shared.global [%0], [%1], 16;" :: "r"(dst), "l"(src));
}
__device__ __forceinline__ void ldsm_x4(uint32_t addr, uint32_t* r) {
    asm volatile("ldmatrix.sync.aligned.m8n8.x4.shared.b16 {%0,%1,%2,%3}, [%4];"
        : "=r"(r[0]), "=r"(r[1]), "=r"(r[2]), "=r"(r[3]) : "r"(addr));
}
__device__ __forceinline__ void ldsm_x2(uint32_t addr, uint32_t* r) {
    asm volatile("ldmatrix.sync.aligned.m8n8.x2.shared.b16 {%0,%1}, [%2];"
        : "=r"(r[0]), "=r"(r[1]) : "r"(addr));
}
__device__ __forceinline__ void ldsm_x2t(uint32_t addr, uint32_t* r) {
    asm volatile("ldmatrix.sync.aligned.m8n8.x2.trans.shared.b16 {%0,%1}, [%2];"
        : "=r"(r[0]), "=r"(r[1]) : "r"(addr));
}
__device__ __forceinline__ void mma_bf16(float* c, const uint32_t* a, const uint32_t* b) {
    asm volatile("mma.sync.aligned.m16n8k16.row.col.f32.bf16.bf16.f32 "
        "{%0,%1,%2,%3}, {%4,%5,%6,%7}, {%8,%9}, {%0,%1,%2,%3};"
        : "+f"(c[0]), "+f"(c[1]), "+f"(c[2]), "+f"(c[3])
        : "r"(a[0]), "r"(a[1]), "r"(a[2]), "r"(a[3]), "r"(b[0]), "r"(b[1]));
}
__device__ __forceinline__ void mma_f16(float* c, const uint32_t* a, const uint32_t* b) {
    asm volatile("mma.sync.aligned.m16n8k16.row.col.f32.f16.f16.f32 "
        "{%0,%1,%2,%3}, {%4,%5,%6,%7}, {%8,%9}, {%0,%1,%2,%3};"
        : "+f"(c[0]), "+f"(c[1]), "+f"(c[2]), "+f"(c[3])
        : "r"(a[0]), "r"(a[1]), "r"(a[2]), "r"(a[3]), "r"(b[0]), "r"(b[1]));
}

// ---------------- split fp32 [R][2048] -> extended bf16 [R][6144] ----------------
__global__ void split_ext(const float* __restrict__ src, __nv_bfloat16* __restrict__ dst,
                          int n4, int hi2_off, int lo_off) {
    int i = blockIdx.x * blockDim.x + threadIdx.x;
    if (i >= n4) return;
    int c4 = (i & 511) << 2;
    int r  = i >> 9;
    float4 v = *(const float4*)(src + (size_t)r * EMB + c4);
    __nv_bfloat16 h0 = __float2bfloat16(v.x), h1 = __float2bfloat16(v.y);
    __nv_bfloat16 h2 = __float2bfloat16(v.z), h3 = __float2bfloat16(v.w);
    __nv_bfloat16 l0 = __float2bfloat16(v.x - __bfloat162float(h0));
    __nv_bfloat16 l1 = __float2bfloat16(v.y - __bfloat162float(h1));
    __nv_bfloat16 l2 = __float2bfloat16(v.z - __bfloat162float(h2));
    __nv_bfloat16 l3 = __float2bfloat16(v.w - __bfloat162float(h3));
    __nv_bfloat162 H01(h0, h1), H23(h2, h3), L01(l0, l1), L23(l2, l3);
    size_t rowb = (size_t)r * KEXT;
    __nv_bfloat162* p0 = (__nv_bfloat162*)(dst + rowb + c4);
    __nv_bfloat162* p1 = (__nv_bfloat162*)(dst + rowb + hi2_off + c4);
    __nv_bfloat162* p2 = (__nv_bfloat162*)(dst + rowb + lo_off + c4);
    p0[0] = H01; p0[1] = H23;
    p1[0] = H01; p1[1] = H23;
    p2[0] = L01; p2[1] = L23;
}

// ---------------- HMMA GEMM: C[M,N] = A[M,KEXT] @ B[N,KEXT]^T ----------------
#define GEMM_SMEM (3 * 32768)
__global__ __launch_bounds__(256, 1) void gemm_hmma(
    const __nv_bfloat16* __restrict__ A, const __nv_bfloat16* __restrict__ B,
    float* __restrict__ C, int N) {
    extern __shared__ __align__(1024) char smem[];
    const uint32_t sbase = smem_u32(smem);
    const int tid = threadIdx.x;
    const int wid = tid >> 5, lane = tid & 31;
    const int bm = blockIdx.y * 128, bn = blockIdx.x * 128;
    const int warp_m = wid & 3, warp_n = wid >> 2;

    auto load_chunk = [&](int chunk, int stage) {
        const uint32_t sA = sbase + stage * 32768;
        const uint32_t sB = sA + 16384;
#pragma unroll
        for (int i = 0; i < 4; i++) {
            int id = i * 256 + tid;
            int row = id >> 3, c16 = id & 7;
            uint32_t off = (uint32_t)(row * 128 + ((c16 ^ (row & 7)) << 4));
            cp16(sA + off, A + (size_t)(bm + row) * KEXT + chunk * GBK + c16 * 8);
        }
#pragma unroll
        for (int i = 0; i < 4; i++) {
            int id = i * 256 + tid;
            int row = id >> 3, c16 = id & 7;
            uint32_t off = (uint32_t)(row * 128 + ((c16 ^ (row & 7)) << 4));
            cp16(sB + off, B + (size_t)(bn + row) * KEXT + chunk * GBK + c16 * 8);
        }
        asm volatile("cp.async.commit_group;" ::: "memory");
    };

    float acc[2][8][4];
#pragma unroll
    for (int mf = 0; mf < 2; mf++)
#pragma unroll
        for (int nf = 0; nf < 8; nf++)
#pragma unroll
            for (int q = 0; q < 4; q++) acc[mf][nf][q] = 0.f;

    load_chunk(0, 0);
    load_chunk(1, 1);

    for (int c = 0; c < NCH; c++) {
        __syncthreads();
        if (c + 2 < NCH) load_chunk(c + 2, (c + 2) % 3);
        else asm volatile("cp.async.commit_group;" ::: "memory");
        asm volatile("cp.async.wait_group 2;" ::: "memory");
        __syncthreads();

        const uint32_t sA = sbase + (c % 3) * 32768;
        const uint32_t sB = sA + 16384;
#pragma unroll
        for (int kf = 0; kf < 4; kf++) {
            uint32_t afr[2][4];
#pragma unroll
            for (int mf = 0; mf < 2; mf++) {
                int row = warp_m * 32 + mf * 16 + (lane & 15);
                int c16 = kf * 2 + (lane >> 4);
                ldsm_x4(sA + row * 128 + ((c16 ^ (row & 7)) << 4), afr[mf]);
            }
#pragma unroll
            for (int nf = 0; nf < 8; nf++) {
                uint32_t bfr[2];
                int nrow = warp_n * 64 + nf * 8 + (lane & 7);
                int c16 = kf * 2 + ((lane >> 3) & 1);
                ldsm_x2(sB + nrow * 128 + ((c16 ^ (nrow & 7)) << 4), bfr);
                mma_bf16(acc[0][nf], afr[0], bfr);
                mma_bf16(acc[1][nf], afr[1], bfr);
            }
        }
    }

#pragma unroll
    for (int mf = 0; mf < 2; mf++) {
        int row = bm + warp_m * 32 + mf * 16 + (lane >> 2);
#pragma unroll
        for (int nf = 0; nf < 8; nf++) {
            int col = bn + warp_n * 64 + nf * 8 + (lane & 3) * 2;
            *(float2*)(C + (size_t)row * N + col)       = make_float2(acc[mf][nf][0], acc[mf][nf][1]);
            *(float2*)(C + (size_t)(row + 8) * N + col) = make_float2(acc[mf][nf][2], acc[mf][nf][3]);
        }
    }
}

// ---------------- RoPE + scatter qkv -> fp16 q(hi,lo)/k/v ----------------
__global__ void rope_scatter(const float* __restrict__ qkv,
                             const float* __restrict__ cosb,
                             const float* __restrict__ sinb) {
    int idx = blockIdx.x * blockDim.x + threadIdx.x;
    const int total = BT_TOTAL * NG * 6 * 32;
    if (idx >= total) return;
    int dh = idx & 31;
    int r = idx >> 5;
    int slot = r % 6; r /= 6;
    int g = r % NG;   r /= NG;
    int bt = r;
    int t = bt & (T_SEQ - 1);
    int b = bt >> 11;

    const float* src = qkv + (size_t)bt * FD + (g * 6 + slot) * HD;
    float x1 = src[dh], x2 = src[dh + 32];
    if (slot == 5) {
        __half* dst = g_vh + ((size_t)(b * NG + g) * T_SEQ + t) * HD;
        dst[dh] = __float2half_rn(x1); dst[dh + 32] = __float2half_rn(x2);
    } else {
        float c = cosb[t * 32 + dh], s = sinb[t * 32 + dh];
        float y1 = x1 * c - x2 * s;
        float y2 = x2 * c + x1 * s;
        if (slot == 4) {
            __half* dst = g_kh + ((size_t)(b * NG + g) * T_SEQ + t) * HD;
            dst[dh] = __float2half_rn(y1); dst[dh + 32] = __float2half_rn(y2);
        } else {
            size_t o = ((size_t)(b * NH + g * 4 + slot) * T_SEQ + t) * HD;
            __half h1 = __float2half_rn(y1), h2 = __float2half_rn(y2);
            g_qh[o + dh] = h1; g_qh[o + dh + 32] = h2;
            g_ql[o + dh]      = __float2half_rn(y1 - __half2float(h1));
            g_ql[o + dh + 32] = __float2half_rn(y2 - __half2float(h2));
        }
    }
}

// ---------------- HMMA flash attention (fp16, q hi/lo split, non-causal) ----------------
// Br=128, Bc=64, 256 threads (8 warps x 16 q rows). Writes extended bf16 directly.
#define ABR 128
#define ABC 64
#define ATT_SMEM (32768 + 2 * 16384)
__global__ __launch_bounds__(256, 1) void attn_hmma() {
    extern __shared__ __align__(1024) char smem[];
    const uint32_t sb = smem_u32(smem);
    const uint32_t Qs = sb;            // [128 rows][256B]  (hi c16 0-7 | lo c16 8-15)
    const uint32_t KVs = sb + 32768;   // 2 stages x (K 8192 + V 8192)

    const int tid = threadIdx.x;
    const int w = tid >> 5, lane = tid & 31;
    const int qt = blockIdx.x, bh = blockIdx.y;
    const int b = bh >> 5, h = bh & 31, g = h >> 2;
    const int q0 = qt * ABR;

    const __half* qhb = g_qh + ((size_t)(b * NH + h) * T_SEQ + q0) * HD;
    const __half* qlb = g_ql + ((size_t)(b * NH + h) * T_SEQ + q0) * HD;
    const __half* khb = g_kh + (size_t)(b * NG + g) * T_SEQ * HD;
    const __half* vhb = g_vh + (size_t)(b * NG + g) * T_SEQ * HD;

    // Q load: 128 rows x 16 chunks of 16B
#pragma unroll
    for (int i = 0; i < 8; i++) {
        int id = i * 256 + tid;
        int row = id >> 4, c16 = id & 15;
        uint32_t off = (uint32_t)(row * 256 + ((((c16 ^ row) & 7) | (c16 & 8)) << 4));
        const __half* src = (c16 < 8) ? (qhb + row * 64 + c16 * 8)
                                      : (qlb + row * 64 + (c16 - 8) * 8);
        cp16(Qs + off, src);
    }
    asm volatile("cp.async.commit_group;" ::: "memory");

    auto loadKV = [&](int t, int s) {
        uint32_t base = KVs + s * 16384;
#pragma unroll
        for (int i = 0; i < 2; i++) {
            int id = i * 256 + tid;          // 512 chunks: 64 rows x 8
            int row = id >> 3, c8 = id & 7;
            uint32_t off = (uint32_t)(row * 128 + ((c8 ^ (row & 7)) << 4));
            size_t ga = (size_t)(t * ABC + row) * 64 + c8 * 8;
            cp16(base + off, khb + ga);
            cp16(base + 8192 + off, vhb + ga);
        }
        asm volatile("cp.async.commit_group;" ::: "memory");
    };
    loadKV(0, 0);

    float oacc[8][4];
#pragma unroll
    for (int nf = 0; nf < 8; nf++)
#pragma unroll
        for (int q = 0; q < 4; q++) oacc[nf][q] = 0.f;
    float m0 = -1e30f, m1 = -1e30f, l0 = 0.f, l1 = 0.f;
    const float sc = 0.125f;

    const int NT = T_SEQ / ABC;
    for (int t = 0; t < NT; t++) {
        if (t + 1 < NT) { loadKV(t + 1, (t + 1) & 1); asm volatile("cp.async.wait_group 1;" ::: "memory"); }
        else            { asm volatile("cp.async.wait_group 0;" ::: "memory"); }
        __syncthreads();
        const uint32_t kb = KVs + (t & 1) * 16384;
        const uint32_t vb = kb + 8192;

        // ---- S = Qext @ K^T
        float sacc[8][4];
#pragma unroll
        for (int nf = 0; nf < 8; nf++)
#pragma unroll
            for (int q = 0; q < 4; q++) sacc[nf][q] = 0.f;

#pragma unroll
        for (int kf = 0; kf < 4; kf++) {
            uint32_t ah[4], al[4];
            {
                int row = w * 16 + (lane & 15);
                int c16h = kf * 2 + (lane >> 4);
                int c16l = 8 + kf * 2 + (lane >> 4);
                ldsm_x4(Qs + row * 256 + ((((c16h ^ row) & 7) | (c16h & 8)) << 4), ah);
                ldsm_x4(Qs + row * 256 + ((((c16l ^ row) & 7) | (c16l & 8)) << 4), al);
            }
#pragma unroll
            for (int nf = 0; nf < 8; nf++) {
                uint32_t bk[2];
                int nrow = nf * 8 + (lane & 7);
                int c8 = kf * 2 + ((lane >> 3) & 1);
                ldsm_x2(kb + nrow * 128 + ((c8 ^ (nrow & 7)) << 4), bk);
                mma_f16(sacc[nf], ah, bk);
                mma_f16(sacc[nf], al, bk);
            }
        }

        // ---- online softmax
        float mx0 = -1e30f, mx1 = -1e30f;
#pragma unroll
        for (int nf = 0; nf < 8; nf++) {
            mx0 = fmaxf(mx0, fmaxf(sacc[nf][0], sacc[nf][1]));
            mx1 = fmaxf(mx1, fmaxf(sacc[nf][2], sacc[nf][3]));
        }
        mx0 = fmaxf(mx0, __shfl_xor_sync(0xffffffff, mx0, 1));
        mx0 = fmaxf(mx0, __shfl_xor_sync(0xffffffff, mx0, 2));
        mx1 = fmaxf(mx1, __shfl_xor_sync(0xffffffff, mx1, 1));
        mx1 = fmaxf(mx1, __shfl_xor_sync(0xffffffff, mx1, 2));
        float mn0 = fmaxf(m0, mx0 * sc);
        float mn1 = fmaxf(m1, mx1 * sc);
        float a0 = __expf(m0 - mn0), a1 = __expf(m1 - mn1);
        m0 = mn0; m1 = mn1;

        uint32_t pa[16];
        float s0 = 0.f, s1 = 0.f;
#pragma unroll
        for (int nf = 0; nf < 8; nf++) {
            float p0 = __expf(sacc[nf][0] * sc - mn0);
            float p1 = __expf(sacc[nf][1] * sc - mn0);
            float p2 = __expf(sacc[nf][2] * sc - mn1);
            float p3 = __expf(sacc[nf][3] * sc - mn1);
            s0 += p0 + p1; s1 += p2 + p3;
            __half2 h01 = __floats2half2_rn(p0, p1);
            __half2 h23 = __floats2half2_rn(p2, p3);
            pa[2 * nf]     = *(uint32_t*)&h01;
            pa[2 * nf + 1] = *(uint32_t*)&h23;
        }
        l0 = l0 * a0 + s0;
        l1 = l1 * a1 + s1;
#pragma unroll
        for (int nf = 0; nf < 8; nf++) {
            oacc[nf][0] *= a0; oacc[nf][1] *= a0;
            oacc[nf][2] *= a1; oacc[nf][3] *= a1;
        }

        // ---- O += P @ V   (V via ldmatrix.trans: [key][d] storage)
#pragma unroll
        for (int kf2 = 0; kf2 < 4; kf2++) {
            uint32_t a[4] = { pa[4 * kf2], pa[4 * kf2 + 1], pa[4 * kf2 + 2], pa[4 * kf2 + 3] };
#pragma unroll
            for (int nf = 0; nf < 8; nf++) {
                uint32_t bv[2];
                int vrow = kf2 * 16 + (lane & 15);
                int c8 = nf;
                ldsm_x2t(vb + vrow * 128 + ((c8 ^ (vrow & 7)) << 4), bv);
                mma_f16(oacc[nf], a, bv);
            }
        }
        __syncthreads();
    }

    // final l across quad
    l0 += __shfl_xor_sync(0xffffffff, l0, 1);
    l0 += __shfl_xor_sync(0xffffffff, l0, 2);
    l1 += __shfl_xor_sync(0xffffffff, l1, 1);
    l1 += __shfl_xor_sync(0xffffffff, l1, 2);
    float inv0 = 1.f / l0, inv1 = 1.f / l1;

    // write extended bf16 [hi | lo | hi] directly: row = b*T + q0 + 16w + r, col = h*64 + ...
    int r0 = lane >> 2;
    size_t row0 = (size_t)(b * T_SEQ + q0 + w * 16 + r0) * KEXT;
    size_t row1 = row0 + 8 * KEXT;
#pragma unroll
    for (int nf = 0; nf < 8; nf++) {
        int col = h * 64 + nf * 8 + (lane & 3) * 2;
        float v0 = oacc[nf][0] * inv0, v1 = oacc[nf][1] * inv0;
        float v2 = oacc[nf][2] * inv1, v3 = oacc[nf][3] * inv1;
        __nv_bfloat16 h0 = __float2bfloat16(v0), h1 = __float2bfloat16(v1);
        __nv_bfloat16 h2 = __float2bfloat16(v2), h3 = __float2bfloat16(v3);
        __nv_bfloat162 H01(h0, h1), H23(h2, h3);
        __nv_bfloat162 L01(__float2bfloat16(v0 - __bfloat162float(h0)),
                           __float2bfloat16(v1 - __bfloat162float(h1)));
        __nv_bfloat162 L23(__float2bfloat16(v2 - __bfloat162float(h2)),
                           __float2bfloat16(v3 - __bfloat162float(h3)));
        *(__nv_bfloat162*)(g_ae + row0 + col)            = H01;
        *(__nv_bfloat162*)(g_ae + row0 + 2 * EMB + col)  = H01;
        *(__nv_bfloat162*)(g_ae + row0 + EMB + col)      = L01;
        *(__nv_bfloat162*)(g_ae + row1 + col)            = H23;
        *(__nv_bfloat162*)(g_ae + row1 + 2 * EMB + col)  = H23;
        *(__nv_bfloat162*)(g_ae + row1 + EMB + col)      = L23;
    }
}

// ---------------- launch ----------------
extern "C" void kernel_launch(void* const* d_in, const int* in_sizes, int n_in,
                              void* d_out, int out_size) {
    const float* x      = (const float*)d_in[0];
    const float* cosb   = (const float*)d_in[1];
    const float* sinb   = (const float*)d_in[2];
    const float* attn_w = (const float*)d_in[3];
    const float* proj_w = (const float*)d_in[4];
    float* out = (float*)d_out;

    float* qkv;
    __nv_bfloat16 *xe, *w1e, *w2e, *ae;
    cudaGetSymbolAddress((void**)&qkv, g_qkv);
    cudaGetSymbolAddress((void**)&xe, g_xe);
    cudaGetSymbolAddress((void**)&w1e, g_w1e);
    cudaGetSymbolAddress((void**)&w2e, g_w2e);
    cudaGetSymbolAddress((void**)&ae, g_ae);

    cudaFuncSetAttribute(gemm_hmma, cudaFuncAttributeMaxDynamicSharedMemorySize, GEMM_SMEM);
    cudaFuncSetAttribute(attn_hmma, cudaFuncAttributeMaxDynamicSharedMemorySize, ATT_SMEM);

    {
        int n4 = BT_TOTAL * 512;
        split_ext<<<(n4 + 255) / 256, 256>>>(x, xe, n4, 2 * EMB, EMB);
        n4 = FD * 512;
        split_ext<<<(n4 + 255) / 256, 256>>>(attn_w, w1e, n4, EMB, 2 * EMB);
        n4 = EMB * 512;
        split_ext<<<(n4 + 255) / 256, 256>>>(proj_w, w2e, n4, EMB, 2 * EMB);
    }

    // 1) qkv = x @ attn_w^T
    gemm_hmma<<<dim3(FD / 128, BT_TOTAL / 128), 256, GEMM_SMEM>>>(xe, w1e, qkv, FD);

    // 2) rope + scatter to fp16
    {
        int total = BT_TOTAL * NG * 6 * 32;
        rope_scatter<<<(total + 255) / 256, 256>>>(qkv, cosb, sinb);
    }

    // 3) HMMA flash attention -> g_ae (extended bf16, direct)
    attn_hmma<<<dim3(T_SEQ / ABR, 2 * NH), 256, ATT_SMEM>>>();

    // 4) out = att @ proj_w^T
    gemm_hmma<<<dim3(EMB / 128, BT_TOTAL / 128), 256, GEMM_SMEM>>>(ae, w2e, out, EMB);
}

// round 9
// speedup vs baseline: 3.6450x; 1.0959x over previous
#include <cuda_runtime.h>
#include <cuda_bf16.h>
#include <cuda_fp16.h>
#include <cstdint>

#define BT_TOTAL 4096
#define T_SEQ    2048
#define EMB      2048
#define FD       3072
#define NH       32
#define NG       8
#define HD       64
#define KEXT     6144           // 3 * EMB (hi | lo | hi) extended K
#define GBK      64
#define NCH      (KEXT / GBK)   // 96

// ---------------- device scratch (no allocations allowed) ----------------
__device__ float g_qkv[(size_t)BT_TOTAL * FD];

__device__ __half g_qh[(size_t)2 * NH * T_SEQ * HD];
__device__ __half g_ql[(size_t)2 * NH * T_SEQ * HD];
__device__ __half g_kh[(size_t)2 * NG * T_SEQ * HD];
__device__ __half g_vh[(size_t)2 * NG * T_SEQ * HD];

__device__ __nv_bfloat16 g_xe[(size_t)BT_TOTAL * KEXT];   // x extended
__device__ __nv_bfloat16 g_w1e[(size_t)FD * KEXT];        // attn_w extended
__device__ __nv_bfloat16 g_w2e[(size_t)EMB * KEXT];       // proj_w extended
__device__ __nv_bfloat16 g_ae[(size_t)BT_TOTAL * KEXT];   // att extended

// ---------------- helpers ----------------
__device__ __forceinline__ uint32_t smem_u32(const void* p) {
    uint32_t a;
    asm("{ .reg .u64 t; cvta.to.shared.u64 t, %1; cvt.u32.u64 %0, t; }" : "=r"(a) : "l"(p));
    return a;
}
__device__ __forceinline__ void cp16(uint32_t dst, const void* src) {
    asm volatile("cp.async.cg.shared.global [%0], [%1], 16;" :: "r"(dst), "l"(src));
}
__device__ __forceinline__ void ldsm_x4(uint32_t addr, uint32_t* r) {
    asm volatile("ldmatrix.sync.aligned.m8n8.x4.shared.b16 {%0,%1,%2,%3}, [%4];"
        : "=r"(r[0]), "=r"(r[1]), "=r"(r[2]), "=r"(r[3]) : "r"(addr));
}
__device__ __forceinline__ void ldsm_x2(uint32_t addr, uint32_t* r) {
    asm volatile("ldmatrix.sync.aligned.m8n8.x2.shared.b16 {%0,%1}, [%2];"
        : "=r"(r[0]), "=r"(r[1]) : "r"(addr));
}
__device__ __forceinline__ void ldsm_x2t(uint32_t addr, uint32_t* r) {
    asm volatile("ldmatrix.sync.aligned.m8n8.x2.trans.shared.b16 {%0,%1}, [%2];"
        : "=r"(r[0]), "=r"(r[1]) : "r"(addr));
}
__device__ __forceinline__ void mma_bf16(float* c, const uint32_t* a, const uint32_t* b) {
    asm volatile("mma.sync.aligned.m16n8k16.row.col.f32.bf16.bf16.f32 "
        "{%0,%1,%2,%3}, {%4,%5,%6,%7}, {%8,%9}, {%0,%1,%2,%3};"
        : "+f"(c[0]), "+f"(c[1]), "+f"(c[2]), "+f"(c[3])
        : "r"(a[0]), "r"(a[1]), "r"(a[2]), "r"(a[3]), "r"(b[0]), "r"(b[1]));
}
__device__ __forceinline__ void mma_f16(float* c, const uint32_t* a, const uint32_t* b) {
    asm volatile("mma.sync.aligned.m16n8k16.row.col.f32.f16.f16.f32 "
        "{%0,%1,%2,%3}, {%4,%5,%6,%7}, {%8,%9}, {%0,%1,%2,%3};"
        : "+f"(c[0]), "+f"(c[1]), "+f"(c[2]), "+f"(c[3])
        : "r"(a[0]), "r"(a[1]), "r"(a[2]), "r"(a[3]), "r"(b[0]), "r"(b[1]));
}

// ---------------- split fp32 [R][2048] -> extended bf16 [R][6144] ----------------
__global__ void split_ext(const float* __restrict__ src, __nv_bfloat16* __restrict__ dst,
                          int n4, int hi2_off, int lo_off) {
    int i = blockIdx.x * blockDim.x + threadIdx.x;
    if (i >= n4) return;
    int c4 = (i & 511) << 2;
    int r  = i >> 9;
    float4 v = *(const float4*)(src + (size_t)r * EMB + c4);
    __nv_bfloat16 h0 = __float2bfloat16(v.x), h1 = __float2bfloat16(v.y);
    __nv_bfloat16 h2 = __float2bfloat16(v.z), h3 = __float2bfloat16(v.w);
    __nv_bfloat16 l0 = __float2bfloat16(v.x - __bfloat162float(h0));
    __nv_bfloat16 l1 = __float2bfloat16(v.y - __bfloat162float(h1));
    __nv_bfloat16 l2 = __float2bfloat16(v.z - __bfloat162float(h2));
    __nv_bfloat16 l3 = __float2bfloat16(v.w - __bfloat162float(h3));
    __nv_bfloat162 H01(h0, h1), H23(h2, h3), L01(l0, l1), L23(l2, l3);
    size_t rowb = (size_t)r * KEXT;
    __nv_bfloat162* p0 = (__nv_bfloat162*)(dst + rowb + c4);
    __nv_bfloat162* p1 = (__nv_bfloat162*)(dst + rowb + hi2_off + c4);
    __nv_bfloat162* p2 = (__nv_bfloat162*)(dst + rowb + lo_off + c4);
    p0[0] = H01; p0[1] = H23;
    p1[0] = H01; p1[1] = H23;
    p2[0] = L01; p2[1] = L23;
}

// ---------------- HMMA GEMM: C[M,N] = A[M,KEXT] @ B[N,KEXT]^T ----------------
// 256 threads, CTA tile 256x128, warp tile 64x64 (4x2 warps), BK=64, 3-stage.
#define GSTG 49152                      // A 32KB + B 16KB per stage
#define GEMM_SMEM (3 * GSTG)
__global__ __launch_bounds__(256, 1) void gemm_hmma(
    const __nv_bfloat16* __restrict__ A, const __nv_bfloat16* __restrict__ B,
    float* __restrict__ C, int N) {
    extern __shared__ __align__(1024) char smem[];
    const uint32_t sbase = smem_u32(smem);
    const int tid = threadIdx.x;
    const int wid = tid >> 5, lane = tid & 31;
    const int bm = blockIdx.y * 256, bn = blockIdx.x * 128;
    const int warp_m = wid & 3, warp_n = wid >> 2;   // 4 x 2

    auto load_chunk = [&](int chunk, int stage) {
        const uint32_t sA = sbase + stage * GSTG;
        const uint32_t sB = sA + 32768;
#pragma unroll
        for (int i = 0; i < 8; i++) {                 // A: 256 rows x 8 c16
            int id = i * 256 + tid;
            int row = id >> 3, c16 = id & 7;
            uint32_t off = (uint32_t)(row * 128 + ((c16 ^ (row & 7)) << 4));
            cp16(sA + off, A + (size_t)(bm + row) * KEXT + chunk * GBK + c16 * 8);
        }
#pragma unroll
        for (int i = 0; i < 4; i++) {                 // B: 128 rows x 8 c16
            int id = i * 256 + tid;
            int row = id >> 3, c16 = id & 7;
            uint32_t off = (uint32_t)(row * 128 + ((c16 ^ (row & 7)) << 4));
            cp16(sB + off, B + (size_t)(bn + row) * KEXT + chunk * GBK + c16 * 8);
        }
        asm volatile("cp.async.commit_group;" ::: "memory");
    };

    float acc[4][8][4];
#pragma unroll
    for (int mf = 0; mf < 4; mf++)
#pragma unroll
        for (int nf = 0; nf < 8; nf++)
#pragma unroll
            for (int q = 0; q < 4; q++) acc[mf][nf][q] = 0.f;

    load_chunk(0, 0);
    load_chunk(1, 1);

    for (int c = 0; c < NCH; c++) {
        __syncthreads();
        if (c + 2 < NCH) load_chunk(c + 2, (c + 2) % 3);
        else asm volatile("cp.async.commit_group;" ::: "memory");
        asm volatile("cp.async.wait_group 2;" ::: "memory");
        __syncthreads();

        const uint32_t sA = sbase + (c % 3) * GSTG;
        const uint32_t sB = sA + 32768;
#pragma unroll
        for (int kf = 0; kf < 4; kf++) {
            uint32_t afr[4][4];
#pragma unroll
            for (int mf = 0; mf < 4; mf++) {
                int row = warp_m * 64 + mf * 16 + (lane & 15);
                int c16 = kf * 2 + (lane >> 4);
                ldsm_x4(sA + row * 128 + ((c16 ^ (row & 7)) << 4), afr[mf]);
            }
            uint32_t bfr[4][4];
#pragma unroll
            for (int nf2 = 0; nf2 < 4; nf2++) {
                int nrow = warp_n * 64 + nf2 * 16 + ((lane >> 4) << 3) + (lane & 7);
                int c16 = kf * 2 + ((lane >> 3) & 1);
                ldsm_x4(sB + nrow * 128 + ((c16 ^ (nrow & 7)) << 4), bfr[nf2]);
            }
#pragma unroll
            for (int mf = 0; mf < 4; mf++)
#pragma unroll
                for (int nf2 = 0; nf2 < 4; nf2++) {
                    mma_bf16(acc[mf][2 * nf2],     afr[mf], &bfr[nf2][0]);
                    mma_bf16(acc[mf][2 * nf2 + 1], afr[mf], &bfr[nf2][2]);
                }
        }
    }

    // epilogue
#pragma unroll
    for (int mf = 0; mf < 4; mf++) {
        int row = bm + warp_m * 64 + mf * 16 + (lane >> 2);
#pragma unroll
        for (int nf = 0; nf < 8; nf++) {
            int col = bn + warp_n * 64 + nf * 8 + (lane & 3) * 2;
            *(float2*)(C + (size_t)row * N + col)       = make_float2(acc[mf][nf][0], acc[mf][nf][1]);
            *(float2*)(C + (size_t)(row + 8) * N + col) = make_float2(acc[mf][nf][2], acc[mf][nf][3]);
        }
    }
}

// ---------------- RoPE + scatter qkv -> fp16 q(hi,lo)/k/v ----------------
__global__ void rope_scatter(const float* __restrict__ qkv,
                             const float* __restrict__ cosb,
                             const float* __restrict__ sinb) {
    int idx = blockIdx.x * blockDim.x + threadIdx.x;
    const int total = BT_TOTAL * NG * 6 * 32;
    if (idx >= total) return;
    int dh = idx & 31;
    int r = idx >> 5;
    int slot = r % 6; r /= 6;
    int g = r % NG;   r /= NG;
    int bt = r;
    int t = bt & (T_SEQ - 1);
    int b = bt >> 11;

    const float* src = qkv + (size_t)bt * FD + (g * 6 + slot) * HD;
    float x1 = src[dh], x2 = src[dh + 32];
    if (slot == 5) {
        __half* dst = g_vh + ((size_t)(b * NG + g) * T_SEQ + t) * HD;
        dst[dh] = __float2half_rn(x1); dst[dh + 32] = __float2half_rn(x2);
    } else {
        float c = cosb[t * 32 + dh], s = sinb[t * 32 + dh];
        float y1 = x1 * c - x2 * s;
        float y2 = x2 * c + x1 * s;
        if (slot == 4) {
            __half* dst = g_kh + ((size_t)(b * NG + g) * T_SEQ + t) * HD;
            dst[dh] = __float2half_rn(y1); dst[dh + 32] = __float2half_rn(y2);
        } else {
            size_t o = ((size_t)(b * NH + g * 4 + slot) * T_SEQ + t) * HD;
            __half h1 = __float2half_rn(y1), h2 = __float2half_rn(y2);
            g_qh[o + dh] = h1; g_qh[o + dh + 32] = h2;
            g_ql[o + dh]      = __float2half_rn(y1 - __half2float(h1));
            g_ql[o + dh + 32] = __float2half_rn(y2 - __half2float(h2));
        }
    }
}

// ---------------- HMMA flash attention (fp16, q hi/lo split, non-causal) ----------------
#define ABR 128
#define ABC 64
#define ATT_SMEM (32768 + 2 * 16384)
__global__ __launch_bounds__(256, 1) void attn_hmma() {
    extern __shared__ __align__(1024) char smem[];
    const uint32_t sb = smem_u32(smem);
    const uint32_t Qs = sb;            // [128 rows][256B]  (hi c16 0-7 | lo c16 8-15)
    const uint32_t KVs = sb + 32768;   // 2 stages x (K 8192 + V 8192)

    const int tid = threadIdx.x;
    const int w = tid >> 5, lane = tid & 31;
    const int qt = blockIdx.x, bh = blockIdx.y;
    const int b = bh >> 5, h = bh & 31, g = h >> 2;
    const int q0 = qt * ABR;

    const __half* qhb = g_qh + ((size_t)(b * NH + h) * T_SEQ + q0) * HD;
    const __half* qlb = g_ql + ((size_t)(b * NH + h) * T_SEQ + q0) * HD;
    const __half* khb = g_kh + (size_t)(b * NG + g) * T_SEQ * HD;
    const __half* vhb = g_vh + (size_t)(b * NG + g) * T_SEQ * HD;

#pragma unroll
    for (int i = 0; i < 8; i++) {
        int id = i * 256 + tid;
        int row = id >> 4, c16 = id & 15;
        uint32_t off = (uint32_t)(row * 256 + ((((c16 ^ row) & 7) | (c16 & 8)) << 4));
        const __half* src = (c16 < 8) ? (qhb + row * 64 + c16 * 8)
                                      : (qlb + row * 64 + (c16 - 8) * 8);
        cp16(Qs + off, src);
    }
    asm volatile("cp.async.commit_group;" ::: "memory");

    auto loadKV = [&](int t, int s) {
        uint32_t base = KVs + s * 16384;
#pragma unroll
        for (int i = 0; i < 2; i++) {
            int id = i * 256 + tid;
            int row = id >> 3, c8 = id & 7;
            uint32_t off = (uint32_t)(row * 128 + ((c8 ^ (row & 7)) << 4));
            size_t ga = (size_t)(t * ABC + row) * 64 + c8 * 8;
            cp16(base + off, khb + ga);
            cp16(base + 8192 + off, vhb + ga);
        }
        asm volatile("cp.async.commit_group;" ::: "memory");
    };
    loadKV(0, 0);

    float oacc[8][4];
#pragma unroll
    for (int nf = 0; nf < 8; nf++)
#pragma unroll
        for (int q = 0; q < 4; q++) oacc[nf][q] = 0.f;
    float m0 = -1e30f, m1 = -1e30f, l0 = 0.f, l1 = 0.f;
    const float sc = 0.125f;

    const int NT = T_SEQ / ABC;
    for (int t = 0; t < NT; t++) {
        if (t + 1 < NT) { loadKV(t + 1, (t + 1) & 1); asm volatile("cp.async.wait_group 1;" ::: "memory"); }
        else            { asm volatile("cp.async.wait_group 0;" ::: "memory"); }
        __syncthreads();
        const uint32_t kb = KVs + (t & 1) * 16384;
        const uint32_t vb = kb + 8192;

        float sacc[8][4];
#pragma unroll
        for (int nf = 0; nf < 8; nf++)
#pragma unroll
            for (int q = 0; q < 4; q++) sacc[nf][q] = 0.f;

#pragma unroll
        for (int kf = 0; kf < 4; kf++) {
            uint32_t ah[4], al[4];
            {
                int row = w * 16 + (lane & 15);
                int c16h = kf * 2 + (lane >> 4);
                int c16l = 8 + kf * 2 + (lane >> 4);
                ldsm_x4(Qs + row * 256 + ((((c16h ^ row) & 7) | (c16h & 8)) << 4), ah);
                ldsm_x4(Qs + row * 256 + ((((c16l ^ row) & 7) | (c16l & 8)) << 4), al);
            }
#pragma unroll
            for (int nf = 0; nf < 8; nf++) {
                uint32_t bk[2];
                int nrow = nf * 8 + (lane & 7);
                int c8 = kf * 2 + ((lane >> 3) & 1);
                ldsm_x2(kb + nrow * 128 + ((c8 ^ (nrow & 7)) << 4), bk);
                mma_f16(sacc[nf], ah, bk);
                mma_f16(sacc[nf], al, bk);
            }
        }

        float mx0 = -1e30f, mx1 = -1e30f;
#pragma unroll
        for (int nf = 0; nf < 8; nf++) {
            mx0 = fmaxf(mx0, fmaxf(sacc[nf][0], sacc[nf][1]));
            mx1 = fmaxf(mx1, fmaxf(sacc[nf][2], sacc[nf][3]));
        }
        mx0 = fmaxf(mx0, __shfl_xor_sync(0xffffffff, mx0, 1));
        mx0 = fmaxf(mx0, __shfl_xor_sync(0xffffffff, mx0, 2));
        mx1 = fmaxf(mx1, __shfl_xor_sync(0xffffffff, mx1, 1));
        mx1 = fmaxf(mx1, __shfl_xor_sync(0xffffffff, mx1, 2));
        float mn0 = fmaxf(m0, mx0 * sc);
        float mn1 = fmaxf(m1, mx1 * sc);
        float a0 = __expf(m0 - mn0), a1 = __expf(m1 - mn1);
        m0 = mn0; m1 = mn1;

        uint32_t pa[16];
        float s0 = 0.f, s1 = 0.f;
#pragma unroll
        for (int nf = 0; nf < 8; nf++) {
            float p0 = __expf(sacc[nf][0] * sc - mn0);
            float p1 = __expf(sacc[nf][1] * sc - mn0);
            float p2 = __expf(sacc[nf][2] * sc - mn1);
            float p3 = __expf(sacc[nf][3] * sc - mn1);
            s0 += p0 + p1; s1 += p2 + p3;
            __half2 h01 = __floats2half2_rn(p0, p1);
            __half2 h23 = __floats2half2_rn(p2, p3);
            pa[2 * nf]     = *(uint32_t*)&h01;
            pa[2 * nf + 1] = *(uint32_t*)&h23;
        }
        l0 = l0 * a0 + s0;
        l1 = l1 * a1 + s1;
#pragma unroll
        for (int nf = 0; nf < 8; nf++) {
            oacc[nf][0] *= a0; oacc[nf][1] *= a0;
            oacc[nf][2] *= a1; oacc[nf][3] *= a1;
        }

#pragma unroll
        for (int kf2 = 0; kf2 < 4; kf2++) {
            uint32_t a[4] = { pa[4 * kf2], pa[4 * kf2 + 1], pa[4 * kf2 + 2], pa[4 * kf2 + 3] };
#pragma unroll
            for (int nf = 0; nf < 8; nf++) {
                uint32_t bv[2];
                int vrow = kf2 * 16 + (lane & 15);
                int c8 = nf;
                ldsm_x2t(vb + vrow * 128 + ((c8 ^ (vrow & 7)) << 4), bv);
                mma_f16(oacc[nf], a, bv);
            }
        }
        __syncthreads();
    }

    l0 += __shfl_xor_sync(0xffffffff, l0, 1);
    l0 += __shfl_xor_sync(0xffffffff, l0, 2);
    l1 += __shfl_xor_sync(0xffffffff, l1, 1);
    l1 += __shfl_xor_sync(0xffffffff, l1, 2);
    float inv0 = 1.f / l0, inv1 = 1.f / l1;

    int r0 = lane >> 2;
    size_t row0 = (size_t)(b * T_SEQ + q0 + w * 16 + r0) * KEXT;
    size_t row1 = row0 + 8 * KEXT;
#pragma unroll
    for (int nf = 0; nf < 8; nf++) {
        int col = h * 64 + nf * 8 + (lane & 3) * 2;
        float v0 = oacc[nf][0] * inv0, v1 = oacc[nf][1] * inv0;
        float v2 = oacc[nf][2] * inv1, v3 = oacc[nf][3] * inv1;
        __nv_bfloat16 h0 = __float2bfloat16(v0), h1 = __float2bfloat16(v1);
        __nv_bfloat16 h2 = __float2bfloat16(v2), h3 = __float2bfloat16(v3);
        __nv_bfloat162 H01(h0, h1), H23(h2, h3);
        __nv_bfloat162 L01(__float2bfloat16(v0 - __bfloat162float(h0)),
                           __float2bfloat16(v1 - __bfloat162float(h1)));
        __nv_bfloat162 L23(__float2bfloat16(v2 - __bfloat162float(h2)),
                           __float2bfloat16(v3 - __bfloat162float(h3)));
        *(__nv_bfloat162*)(g_ae + row0 + col)            = H01;
        *(__nv_bfloat162*)(g_ae + row0 + 2 * EMB + col)  = H01;
        *(__nv_bfloat162*)(g_ae + row0 + EMB + col)      = L01;
        *(__nv_bfloat162*)(g_ae + row1 + col)            = H23;
        *(__nv_bfloat162*)(g_ae + row1 + 2 * EMB + col)  = H23;
        *(__nv_bfloat162*)(g_ae + row1 + EMB + col)      = L23;
    }
}

// ---------------- launch ----------------
extern "C" void kernel_launch(void* const* d_in, const int* in_sizes, int n_in,
                              void* d_out, int out_size) {
    const float* x      = (const float*)d_in[0];
    const float* cosb   = (const float*)d_in[1];
    const float* sinb   = (const float*)d_in[2];
    const float* attn_w = (const float*)d_in[3];
    const float* proj_w = (const float*)d_in[4];
    float* out = (float*)d_out;

    float* qkv;
    __nv_bfloat16 *xe, *w1e, *w2e, *ae;
    cudaGetSymbolAddress((void**)&qkv, g_qkv);
    cudaGetSymbolAddress((void**)&xe, g_xe);
    cudaGetSymbolAddress((void**)&w1e, g_w1e);
    cudaGetSymbolAddress((void**)&w2e, g_w2e);
    cudaGetSymbolAddress((void**)&ae, g_ae);

    cudaFuncSetAttribute(gemm_hmma, cudaFuncAttributeMaxDynamicSharedMemorySize, GEMM_SMEM);
    cudaFuncSetAttribute(attn_hmma, cudaFuncAttributeMaxDynamicSharedMemorySize, ATT_SMEM);

    {
        int n4 = BT_TOTAL * 512;
        split_ext<<<(n4 + 255) / 256, 256>>>(x, xe, n4, 2 * EMB, EMB);
        n4 = FD * 512;
        split_ext<<<(n4 + 255) / 256, 256>>>(attn_w, w1e, n4, EMB, 2 * EMB);
        n4 = EMB * 512;
        split_ext<<<(n4 + 255) / 256, 256>>>(proj_w, w2e, n4, EMB, 2 * EMB);
    }

    // 1) qkv = x @ attn_w^T
    gemm_hmma<<<dim3(FD / 128, BT_TOTAL / 256), 256, GEMM_SMEM>>>(xe, w1e, qkv, FD);

    // 2) rope + scatter to fp16
    {
        int total = BT_TOTAL * NG * 6 * 32;
        rope_scatter<<<(total + 255) / 256, 256>>>(qkv, cosb, sinb);
    }

    // 3) HMMA flash attention -> g_ae (extended bf16, direct)
    attn_hmma<<<dim3(T_SEQ / ABR, 2 * NH), 256, ATT_SMEM>>>();

    // 4) out = att @ proj_w^T
    gemm_hmma<<<dim3(EMB / 128, BT_TOTAL / 256), 256, GEMM_SMEM>>>(ae, w2e, out, EMB);
}

// round 11
// speedup vs baseline: 6.6399x; 1.8217x over previous
#include <cuda_runtime.h>
#include <cuda_fp16.h>
#include <cstdint>

#define BT_TOTAL 4096
#define T_SEQ    2048
#define EMB      2048
#define FD       3072
#define NH       32
#define NG       8
#define HD       64
#define GBK      64
#define NCH      (EMB / GBK)    // 32

// ---------------- device scratch (no allocations allowed) ----------------
__device__ float g_qkv[(size_t)BT_TOTAL * FD];

__device__ __half g_qh[(size_t)2 * NH * T_SEQ * HD];
__device__ __half g_ql[(size_t)2 * NH * T_SEQ * HD];
__device__ __half g_kh[(size_t)2 * NG * T_SEQ * HD];
__device__ __half g_vh[(size_t)2 * NG * T_SEQ * HD];

__device__ __half g_xh[(size_t)BT_TOTAL * EMB];
__device__ __half g_w1h[(size_t)FD * EMB];
__device__ __half g_w2h[(size_t)EMB * EMB];
__device__ __half g_atth[(size_t)BT_TOTAL * EMB];

// ---------------- helpers ----------------
__device__ __forceinline__ uint32_t smem_u32(const void* p) {
    uint32_t a;
    asm("{ .reg .u64 t; cvta.to.shared.u64 t, %1; cvt.u32.u64 %0, t; }" : "=r"(a) : "l"(p));
    return a;
}
__device__ __forceinline__ void cp16(uint32_t dst, const void* src) {
    asm volatile("cp.async.cg.shared.global [%0], [%1], 16;" :: "r"(dst), "l"(src));
}
__device__ __forceinline__ void ldsm_x4(uint32_t addr, uint32_t* r) {
    asm volatile("ldmatrix.sync.aligned.m8n8.x4.shared.b16 {%0,%1,%2,%3}, [%4];"
        : "=r"(r[0]), "=r"(r[1]), "=r"(r[2]), "=r"(r[3]) : "r"(addr));
}
__device__ __forceinline__ void ldsm_x2(uint32_t addr, uint32_t* r) {
    asm volatile("ldmatrix.sync.aligned.m8n8.x2.shared.b16 {%0,%1}, [%2];"
        : "=r"(r[0]), "=r"(r[1]) : "r"(addr));
}
__device__ __forceinline__ void ldsm_x2t(uint32_t addr, uint32_t* r) {
    asm volatile("ldmatrix.sync.aligned.m8n8.x2.trans.shared.b16 {%0,%1}, [%2];"
        : "=r"(r[0]), "=r"(r[1]) : "r"(addr));
}
__device__ __forceinline__ void mma_f16(float* c, const uint32_t* a, const uint32_t* b) {
    asm volatile("mma.sync.aligned.m16n8k16.row.col.f32.f16.f16.f32 "
        "{%0,%1,%2,%3}, {%4,%5,%6,%7}, {%8,%9}, {%0,%1,%2,%3};"
        : "+f"(c[0]), "+f"(c[1]), "+f"(c[2]), "+f"(c[3])
        : "r"(a[0]), "r"(a[1]), "r"(a[2]), "r"(a[3]), "r"(b[0]), "r"(b[1]));
}

// ---------------- convert fp32 -> fp16 ----------------
__global__ void to_half(const float* __restrict__ src, __half* __restrict__ dst, int n4) {
    int i = blockIdx.x * blockDim.x + threadIdx.x;
    if (i >= n4) return;
    float4 v = *(const float4*)(src + (size_t)i * 4);
    __half2 a = __floats2half2_rn(v.x, v.y);
    __half2 b = __floats2half2_rn(v.z, v.w);
    ((__half2*)dst)[i * 2]     = a;
    ((__half2*)dst)[i * 2 + 1] = b;
}

// ---------------- fp16 HMMA GEMM: C[M,N] = A[M,EMB] @ B[N,EMB]^T ----------------
// 256 threads, CTA tile 256x128, warp tile 64x64 (4x2 warps), BK=64, 3-stage,
// single __syncthreads per chunk.
#define GSTG 49152                      // A 32KB + B 16KB per stage
#define GEMM_SMEM (3 * GSTG)
__global__ __launch_bounds__(256, 1) void gemm_hmma(
    const __half* __restrict__ A, const __half* __restrict__ B,
    float* __restrict__ C, int N) {
    extern __shared__ __align__(1024) char smem[];
    const uint32_t sbase = smem_u32(smem);
    const int tid = threadIdx.x;
    const int wid = tid >> 5, lane = tid & 31;
    const int bm = blockIdx.y * 256, bn = blockIdx.x * 128;
    const int warp_m = wid & 3, warp_n = wid >> 2;   // 4 x 2

    auto load_chunk = [&](int chunk, int stage) {
        const uint32_t sA = sbase + stage * GSTG;
        const uint32_t sB = sA + 32768;
#pragma unroll
        for (int i = 0; i < 8; i++) {                 // A: 256 rows x 8 c16
            int id = i * 256 + tid;
            int row = id >> 3, c16 = id & 7;
            uint32_t off = (uint32_t)(row * 128 + ((c16 ^ (row & 7)) << 4));
            cp16(sA + off, A + (size_t)(bm + row) * EMB + chunk * GBK + c16 * 8);
        }
#pragma unroll
        for (int i = 0; i < 4; i++) {                 // B: 128 rows x 8 c16
            int id = i * 256 + tid;
            int row = id >> 3, c16 = id & 7;
            uint32_t off = (uint32_t)(row * 128 + ((c16 ^ (row & 7)) << 4));
            cp16(sB + off, B + (size_t)(bn + row) * EMB + chunk * GBK + c16 * 8);
        }
        asm volatile("cp.async.commit_group;" ::: "memory");
    };

    float acc[4][8][4];
#pragma unroll
    for (int mf = 0; mf < 4; mf++)
#pragma unroll
        for (int nf = 0; nf < 8; nf++)
#pragma unroll
            for (int q = 0; q < 4; q++) acc[mf][nf][q] = 0.f;

    load_chunk(0, 0);
    load_chunk(1, 1);

    for (int c = 0; c < NCH; c++) {
        asm volatile("cp.async.wait_group 1;" ::: "memory");
        __syncthreads();
        if (c + 2 < NCH) load_chunk(c + 2, (c + 2) % 3);
        else asm volatile("cp.async.commit_group;" ::: "memory");

        const uint32_t sA = sbase + (c % 3) * GSTG;
        const uint32_t sB = sA + 32768;
#pragma unroll
        for (int kf = 0; kf < 4; kf++) {
            uint32_t afr[4][4];
#pragma unroll
            for (int mf = 0; mf < 4; mf++) {
                int row = warp_m * 64 + mf * 16 + (lane & 15);
                int c16 = kf * 2 + (lane >> 4);
                ldsm_x4(sA + row * 128 + ((c16 ^ (row & 7)) << 4), afr[mf]);
            }
            uint32_t bfr[4][4];
#pragma unroll
            for (int nf2 = 0; nf2 < 4; nf2++) {
                int nrow = warp_n * 64 + nf2 * 16 + ((lane >> 4) << 3) + (lane & 7);
                int c16 = kf * 2 + ((lane >> 3) & 1);
                ldsm_x4(sB + nrow * 128 + ((c16 ^ (nrow & 7)) << 4), bfr[nf2]);
            }
#pragma unroll
            for (int mf = 0; mf < 4; mf++)
#pragma unroll
                for (int nf2 = 0; nf2 < 4; nf2++) {
                    mma_f16(acc[mf][2 * nf2],     afr[mf], &bfr[nf2][0]);
                    mma_f16(acc[mf][2 * nf2 + 1], afr[mf], &bfr[nf2][2]);
                }
        }
    }

    // epilogue
#pragma unroll
    for (int mf = 0; mf < 4; mf++) {
        int row = bm + warp_m * 64 + mf * 16 + (lane >> 2);
#pragma unroll
        for (int nf = 0; nf < 8; nf++) {
            int col = bn + warp_n * 64 + nf * 8 + (lane & 3) * 2;
            *(float2*)(C + (size_t)row * N + col)       = make_float2(acc[mf][nf][0], acc[mf][nf][1]);
            *(float2*)(C + (size_t)(row + 8) * N + col) = make_float2(acc[mf][nf][2], acc[mf][nf][3]);
        }
    }
}

// ---------------- RoPE + scatter qkv -> fp16 q(hi,lo)/k/v ----------------
__global__ void rope_scatter(const float* __restrict__ qkv,
                             const float* __restrict__ cosb,
                             const float* __restrict__ sinb) {
    int idx = blockIdx.x * blockDim.x + threadIdx.x;
    const int total = BT_TOTAL * NG * 6 * 32;
    if (idx >= total) return;
    int dh = idx & 31;
    int r = idx >> 5;
    int slot = r % 6; r /= 6;
    int g = r % NG;   r /= NG;
    int bt = r;
    int t = bt & (T_SEQ - 1);
    int b = bt >> 11;

    const float* src = qkv + (size_t)bt * FD + (g * 6 + slot) * HD;
    float x1 = src[dh], x2 = src[dh + 32];
    if (slot == 5) {
        __half* dst = g_vh + ((size_t)(b * NG + g) * T_SEQ + t) * HD;
        dst[dh] = __float2half_rn(x1); dst[dh + 32] = __float2half_rn(x2);
    } else {
        float c = cosb[t * 32 + dh], s = sinb[t * 32 + dh];
        float y1 = x1 * c - x2 * s;
        float y2 = x2 * c + x1 * s;
        if (slot == 4) {
            __half* dst = g_kh + ((size_t)(b * NG + g) * T_SEQ + t) * HD;
            dst[dh] = __float2half_rn(y1); dst[dh + 32] = __float2half_rn(y2);
        } else {
            size_t o = ((size_t)(b * NH + g * 4 + slot) * T_SEQ + t) * HD;
            __half h1 = __float2half_rn(y1), h2 = __float2half_rn(y2);
            g_qh[o + dh] = h1; g_qh[o + dh + 32] = h2;
            g_ql[o + dh]      = __float2half_rn(y1 - __half2float(h1));
            g_ql[o + dh + 32] = __float2half_rn(y2 - __half2float(h2));
        }
    }
}

// ---------------- HMMA flash attention (fp16, q hi/lo split, non-causal) ----------------
#define ABR 128
#define ABC 64
#define ATT_SMEM (32768 + 2 * 16384)
__global__ __launch_bounds__(256, 1) void attn_hmma() {
    extern __shared__ __align__(1024) char smem[];
    const uint32_t sb = smem_u32(smem);
    const uint32_t Qs = sb;            // [128 rows][256B]  (hi c16 0-7 | lo c16 8-15)
    const uint32_t KVs = sb + 32768;   // 2 stages x (K 8192 + V 8192)

    const int tid = threadIdx.x;
    const int w = tid >> 5, lane = tid & 31;
    const int qt = blockIdx.x, bh = blockIdx.y;
    const int b = bh >> 5, h = bh & 31, g = h >> 2;
    const int q0 = qt * ABR;

    const __half* qhb = g_qh + ((size_t)(b * NH + h) * T_SEQ + q0) * HD;
    const __half* qlb = g_ql + ((size_t)(b * NH + h) * T_SEQ + q0) * HD;
    const __half* khb = g_kh + (size_t)(b * NG + g) * T_SEQ * HD;
    const __half* vhb = g_vh + (size_t)(b * NG + g) * T_SEQ * HD;

#pragma unroll
    for (int i = 0; i < 8; i++) {
        int id = i * 256 + tid;
        int row = id >> 4, c16 = id & 15;
        uint32_t off = (uint32_t)(row * 256 + ((((c16 ^ row) & 7) | (c16 & 8)) << 4));
        const __half* src = (c16 < 8) ? (qhb + row * 64 + c16 * 8)
                                      : (qlb + row * 64 + (c16 - 8) * 8);
        cp16(Qs + off, src);
    }
    asm volatile("cp.async.commit_group;" ::: "memory");

    auto loadKV = [&](int t, int s) {
        uint32_t base = KVs + s * 16384;
#pragma unroll
        for (int i = 0; i < 2; i++) {
            int id = i * 256 + tid;
            int row = id >> 3, c8 = id & 7;
            uint32_t off = (uint32_t)(row * 128 + ((c8 ^ (row & 7)) << 4));
            size_t ga = (size_t)(t * ABC + row) * 64 + c8 * 8;
            cp16(base + off, khb + ga);
            cp16(base + 8192 + off, vhb + ga);
        }
        asm volatile("cp.async.commit_group;" ::: "memory");
    };
    loadKV(0, 0);

    float oacc[8][4];
#pragma unroll
    for (int nf = 0; nf < 8; nf++)
#pragma unroll
        for (int q = 0; q < 4; q++) oacc[nf][q] = 0.f;
    float m0 = -1e30f, m1 = -1e30f, l0 = 0.f, l1 = 0.f;
    const float sc = 0.125f;

    const int NT = T_SEQ / ABC;
    for (int t = 0; t < NT; t++) {
        if (t + 1 < NT) { loadKV(t + 1, (t + 1) & 1); asm volatile("cp.async.wait_group 1;" ::: "memory"); }
        else            { asm volatile("cp.async.wait_group 0;" ::: "memory"); }
        __syncthreads();
        const uint32_t kb = KVs + (t & 1) * 16384;
        const uint32_t vb = kb + 8192;

        float sacc[8][4];
#pragma unroll
        for (int nf = 0; nf < 8; nf++)
#pragma unroll
            for (int q = 0; q < 4; q++) sacc[nf][q] = 0.f;

#pragma unroll
        for (int kf = 0; kf < 4; kf++) {
            uint32_t ah[4], al[4];
            {
                int row = w * 16 + (lane & 15);
                int c16h = kf * 2 + (lane >> 4);
                int c16l = 8 + kf * 2 + (lane >> 4);
                ldsm_x4(Qs + row * 256 + ((((c16h ^ row) & 7) | (c16h & 8)) << 4), ah);
                ldsm_x4(Qs + row * 256 + ((((c16l ^ row) & 7) | (c16l & 8)) << 4), al);
            }
#pragma unroll
            for (int nf = 0; nf < 8; nf++) {
                uint32_t bk[2];
                int nrow = nf * 8 + (lane & 7);
                int c8 = kf * 2 + ((lane >> 3) & 1);
                ldsm_x2(kb + nrow * 128 + ((c8 ^ (nrow & 7)) << 4), bk);
                mma_f16(sacc[nf], ah, bk);
                mma_f16(sacc[nf], al, bk);
            }
        }

        float mx0 = -1e30f, mx1 = -1e30f;
#pragma unroll
        for (int nf = 0; nf < 8; nf++) {
            mx0 = fmaxf(mx0, fmaxf(sacc[nf][0], sacc[nf][1]));
            mx1 = fmaxf(mx1, fmaxf(sacc[nf][2], sacc[nf][3]));
        }
        mx0 = fmaxf(mx0, __shfl_xor_sync(0xffffffff, mx0, 1));
        mx0 = fmaxf(mx0, __shfl_xor_sync(0xffffffff, mx0, 2));
        mx1 = fmaxf(mx1, __shfl_xor_sync(0xffffffff, mx1, 1));
        mx1 = fmaxf(mx1, __shfl_xor_sync(0xffffffff, mx1, 2));
        float mn0 = fmaxf(m0, mx0 * sc);
        float mn1 = fmaxf(m1, mx1 * sc);
        float a0 = __expf(m0 - mn0), a1 = __expf(m1 - mn1);
        m0 = mn0; m1 = mn1;

        uint32_t pa[16];
        float s0 = 0.f, s1 = 0.f;
#pragma unroll
        for (int nf = 0; nf < 8; nf++) {
            float p0 = __expf(sacc[nf][0] * sc - mn0);
            float p1 = __expf(sacc[nf][1] * sc - mn0);
            float p2 = __expf(sacc[nf][2] * sc - mn1);
            float p3 = __expf(sacc[nf][3] * sc - mn1);
            s0 += p0 + p1; s1 += p2 + p3;
            __half2 h01 = __floats2half2_rn(p0, p1);
            __half2 h23 = __floats2half2_rn(p2, p3);
            pa[2 * nf]     = *(uint32_t*)&h01;
            pa[2 * nf + 1] = *(uint32_t*)&h23;
        }
        l0 = l0 * a0 + s0;
        l1 = l1 * a1 + s1;
#pragma unroll
        for (int nf = 0; nf < 8; nf++) {
            oacc[nf][0] *= a0; oacc[nf][1] *= a0;
            oacc[nf][2] *= a1; oacc[nf][3] *= a1;
        }

#pragma unroll
        for (int kf2 = 0; kf2 < 4; kf2++) {
            uint32_t a[4] = { pa[4 * kf2], pa[4 * kf2 + 1], pa[4 * kf2 + 2], pa[4 * kf2 + 3] };
#pragma unroll
            for (int nf = 0; nf < 8; nf++) {
                uint32_t bv[2];
                int vrow = kf2 * 16 + (lane & 15);
                int c8 = nf;
                ldsm_x2t(vb + vrow * 128 + ((c8 ^ (vrow & 7)) << 4), bv);
                mma_f16(oacc[nf], a, bv);
            }
        }
        __syncthreads();
    }

    l0 += __shfl_xor_sync(0xffffffff, l0, 1);
    l0 += __shfl_xor_sync(0xffffffff, l0, 2);
    l1 += __shfl_xor_sync(0xffffffff, l1, 1);
    l1 += __shfl_xor_sync(0xffffffff, l1, 2);
    float inv0 = 1.f / l0, inv1 = 1.f / l1;

    // write fp16 att [B*T][EMB]
    int r0 = lane >> 2;
    size_t row0 = (size_t)(b * T_SEQ + q0 + w * 16 + r0) * EMB;
    size_t row1 = row0 + 8 * EMB;
#pragma unroll
    for (int nf = 0; nf < 8; nf++) {
        int col = h * 64 + nf * 8 + (lane & 3) * 2;
        __half2 o01 = __floats2half2_rn(oacc[nf][0] * inv0, oacc[nf][1] * inv0);
        __half2 o23 = __floats2half2_rn(oacc[nf][2] * inv1, oacc[nf][3] * inv1);
        *(__half2*)(g_atth + row0 + col) = o01;
        *(__half2*)(g_atth + row1 + col) = o23;
    }
}

// ---------------- launch ----------------
extern "C" void kernel_launch(void* const* d_in, const int* in_sizes, int n_in,
                              void* d_out, int out_size) {
    const float* x      = (const float*)d_in[0];
    const float* cosb   = (const float*)d_in[1];
    const float* sinb   = (const float*)d_in[2];
    const float* attn_w = (const float*)d_in[3];
    const float* proj_w = (const float*)d_in[4];
    float* out = (float*)d_out;

    float* qkv;
    __half *xh, *w1h, *w2h, *atth;
    cudaGetSymbolAddress((void**)&qkv, g_qkv);
    cudaGetSymbolAddress((void**)&xh, g_xh);
    cudaGetSymbolAddress((void**)&w1h, g_w1h);
    cudaGetSymbolAddress((void**)&w2h, g_w2h);
    cudaGetSymbolAddress((void**)&atth, g_atth);

    cudaFuncSetAttribute(gemm_hmma, cudaFuncAttributeMaxDynamicSharedMemorySize, GEMM_SMEM);
    cudaFuncSetAttribute(attn_hmma, cudaFuncAttributeMaxDynamicSharedMemorySize, ATT_SMEM);

    // convert inputs to fp16
    {
        int n4 = BT_TOTAL * EMB / 4;
        to_half<<<(n4 + 255) / 256, 256>>>(x, xh, n4);
        n4 = FD * EMB / 4;
        to_half<<<(n4 + 255) / 256, 256>>>(attn_w, w1h, n4);
        n4 = EMB * EMB / 4;
        to_half<<<(n4 + 255) / 256, 256>>>(proj_w, w2h, n4);
    }

    // 1) qkv = x @ attn_w^T
    gemm_hmma<<<dim3(FD / 128, BT_TOTAL / 256), 256, GEMM_SMEM>>>(xh, w1h, qkv, FD);

    // 2) rope + scatter to fp16
    {
        int total = BT_TOTAL * NG * 6 * 32;
        rope_scatter<<<(total + 255) / 256, 256>>>(qkv, cosb, sinb);
    }

    // 3) HMMA flash attention -> g_atth (fp16)
    attn_hmma<<<dim3(T_SEQ / ABR, 2 * NH), 256, ATT_SMEM>>>();

    // 4) out = att @ proj_w^T
    gemm_hmma<<<dim3(EMB / 128, BT_TOTAL / 256), 256, GEMM_SMEM>>>(atth, w2h, out, EMB);
}